// round 16
// baseline (speedup 1.0000x reference)
#include <cuda_runtime.h>
#include <cuda_fp16.h>
#include <cstdint>

// ============================================================================
// CAAN rank-gated attention (sm_100 base: mma.sync fp16 + cp.async):
//   Q,K = fp16( S Wq^T/Wk^T + b )  single-product fp16 HMMA; proj converts
//   fp32 S -> swizzled fp16 smem on the fly and computes f[i]=S[i].u+c inline
//   gate2[d] = log2(e)/sqrt(128) * sigmoid(rank_emb[d].wL+bL)
//   p_ij = exp2( gate2[|ri-rj|/4] * (q_i.k_j) )   (no-max softmax; |arg| small)
//   out_i = sigmoid( (sum_j p f_j)/(sum_j p) + wf_b )
// R15 post-mortem: combine_kernel = 4.7us of pure launch/latency tail for
// ~50K FLOPs. R16 fuses it into attn: last-arriving chunk-CTA per qblock
// (threadfence + atomic counter) combines the 4 partials and writes out.
// Pipeline: prep -> proj -> attn (3 kernels).
// ============================================================================

#define N_ASSETS 4096
#define D_MODEL  512
#define DK       128
#define NUM_EMB  1024
#define NCHUNK   4
#define KEYS_PER_CHUNK (N_ASSETS / NCHUNK)
#define GATE_MUL    0.1275174677682657f      // (1/sqrt(128)) * log2(e)

typedef unsigned long long ull;

// --------------------------- scratch (no allocs) ----------------------------
__device__ __align__(16) __half d_Wf[256 * D_MODEL];   // rows 0-127 Wq, 128-255 Wk
__device__ __align__(16) __half d_Q[N_ASSETS * DK];
__device__ __align__(16) __half d_K[N_ASSETS * DK];
__device__ float d_f[N_ASSETS];
__device__ float d_u[D_MODEL + 1];
__device__ float d_gate[NUM_EMB];            // premultiplied by GATE_MUL
__device__ float d_pl[NCHUNK * N_ASSETS];
__device__ float d_pw[NCHUNK * N_ASSETS];
__device__ int   d_cnt[64];                  // per-qblock arrival counters (self-resetting)

// --------------------------- mma/ldsm/cp.async helpers -----------------------
__device__ __forceinline__ uint32_t smem_u32(const void* p) {
    uint32_t a;
    asm("{ .reg .u64 t; cvta.to.shared.u64 t, %1; cvt.u32.u64 %0, t; }"
        : "=r"(a) : "l"(p));
    return a;
}
__device__ __forceinline__ void ldsm4(uint32_t* r, uint32_t addr) {
    asm volatile("ldmatrix.sync.aligned.m8n8.x4.shared.b16 {%0,%1,%2,%3}, [%4];"
                 : "=r"(r[0]), "=r"(r[1]), "=r"(r[2]), "=r"(r[3]) : "r"(addr));
}
__device__ __forceinline__ void mma_f16(float* c, const uint32_t* a, const uint32_t* b) {
    asm volatile(
        "mma.sync.aligned.m16n8k16.row.col.f32.f16.f16.f32 "
        "{%0,%1,%2,%3}, {%4,%5,%6,%7}, {%8,%9}, {%0,%1,%2,%3};"
        : "+f"(c[0]), "+f"(c[1]), "+f"(c[2]), "+f"(c[3])
        : "r"(a[0]), "r"(a[1]), "r"(a[2]), "r"(a[3]), "r"(b[0]), "r"(b[1]));
}
__device__ __forceinline__ void cp16(uint32_t dst, const void* src) {
    asm volatile("cp.async.cg.shared.global [%0], [%1], 16;" :: "r"(dst), "l"(src));
}
__device__ __forceinline__ void cp4(uint32_t dst, const void* src) {
    asm volatile("cp.async.ca.shared.global [%0], [%1], 4;" :: "r"(dst), "l"(src));
}
#define CP_COMMIT() asm volatile("cp.async.commit_group;" ::: "memory")
#define CP_WAIT0()  asm volatile("cp.async.wait_group 0;" ::: "memory")

// XOR swizzle of 16B-chunk index within a 256B row (16 chunks)
__device__ __forceinline__ int swz(int chunk, int row) {
    return (chunk & 8) | ((chunk ^ row) & 7);
}

// ============================================================================
// prep: gate (b 0-3), u (b 4-35: 32 blocks, 16-way k-split), c (b 36),
//       W fp16 convert (b 37-100)
// ============================================================================
__global__ void prep_kernel(const float* __restrict__ rank_emb,
                            const float* __restrict__ wL_w,
                            const float* __restrict__ wL_b,
                            const float* __restrict__ Wv_w,
                            const float* __restrict__ wf_w,
                            const float* __restrict__ Wv_b,
                            const float* __restrict__ Wq_w,
                            const float* __restrict__ Wk_w) {
    int b = blockIdx.x, t = threadIdx.x;
    if (b < 4) {
        int d = b * 256 + t;
        float s = wL_b[0];
        #pragma unroll 8
        for (int e = 0; e < 32; e++) s += rank_emb[d * 32 + e] * wL_w[e];
        d_gate[d] = GATE_MUL / (1.0f + __expf(-s));
    } else if (b < 36) {
        int b2 = b - 4;
        int mloc = t & 15, oo = t >> 4;
        int m = b2 * 16 + mloc;
        float s = 0.f;
        #pragma unroll 4
        for (int o = oo; o < D_MODEL; o += 16) s += Wv_w[o * D_MODEL + m] * wf_w[o];
        __shared__ float red[256];
        red[t] = s; __syncthreads();
        if (t < 16) {
            float x = red[t];
            #pragma unroll
            for (int i = 1; i < 16; i++) x += red[t + 16 * i];
            d_u[m] = x;
        }
    } else if (b == 36) {
        __shared__ float red[256];
        float s = 0.f;
        for (int o = t; o < D_MODEL; o += 256) s += wf_w[o] * Wv_b[o];
        red[t] = s; __syncthreads();
        for (int st = 128; st > 0; st >>= 1) {
            if (t < st) red[t] += red[t + st];
            __syncthreads();
        }
        if (t == 0) d_u[D_MODEL] = red[0];
    } else {
        int g0 = (b - 37) * 2048 + t * 8;
        #pragma unroll
        for (int j = 0; j < 2; j++) {
            float4 v = (g0 + 4 * j < 65536)
                ? *(const float4*)(Wq_w + g0 + 4 * j)
                : *(const float4*)(Wk_w + g0 + 4 * j - 65536);
            __half2* dst = (__half2*)(d_Wf + g0 + 4 * j);
            dst[0] = __floats2half2_rn(v.x, v.y);
            dst[1] = __floats2half2_rn(v.z, v.w);
        }
    }
}

// ============================================================================
// proj_mma: Q/K = fp16( S @ W^T + b ). Stages fp32 S via cp.async, converts
// to swizzled fp16 smem in-kernel, computes f[i]=S[i].u+c inline (by==0).
// grid (64 M-tiles of 64 rows, 2 = {Q,K}), 256 thr = 8 warps (2M x 4N).
// ============================================================================
#define PJ_BIAS   0          // 512B
#define PJ_U      512        // 513 floats (u + c)
#define PJ_STG    4096
#define PJ_STRIDE 81920      // SF16 16K | W 32K | S32 32K
#define PJ_SF16   0
#define PJ_W      16384
#define PJ_S32    49152
#define PJ_TOTAL  (4096 + 2 * 81920)   // 167936

__device__ __forceinline__ void pj_copy_stage(uint32_t stg, const float* __restrict__ S,
                                              int mbase, int by, int kc) {
    int tid = threadIdx.x;
    #pragma unroll
    for (int i = 0; i < 8; i++) {
        int idx = tid + 256 * i;
        int row = idx >> 4, c = idx & 15;
        const __half* g = d_Wf + (size_t)(by * 128 + row) * D_MODEL + kc * 128 + c * 8;
        cp16(stg + PJ_W + row * 256 + swz(c, row) * 16, g);
    }
    #pragma unroll
    for (int i = 0; i < 8; i++) {
        int idx = tid + 256 * i;
        int row = idx >> 5, c = idx & 31;
        const float* g = S + (size_t)(mbase + row) * D_MODEL + kc * 128 + c * 4;
        cp16(stg + PJ_S32 + row * 512 + c * 16, g);
    }
}

__global__ void __launch_bounds__(256, 1) proj_mma_kernel(
    const float* __restrict__ S,
    const float* __restrict__ Wq_b, const float* __restrict__ Wk_b) {
    extern __shared__ __align__(1024) char smem[];
    uint32_t sb = smem_u32(smem);
    float* bias_s = (float*)(smem + PJ_BIAS);
    float* u_s    = (float*)(smem + PJ_U);

    int tid = threadIdx.x;
    int w = tid >> 5, lane = tid & 31;
    int wm = w >> 2, wn = w & 3;
    int mbase = blockIdx.x * 64;
    int by = blockIdx.y;                 // 0 = Q, 1 = K

    if (tid < 128) bias_s[tid] = (by ? Wk_b : Wq_b)[tid];
    u_s[tid] = d_u[tid];
    u_s[tid + 256] = d_u[tid + 256];

    float acc[2][4][4];
    #pragma unroll
    for (int mi = 0; mi < 2; mi++)
        #pragma unroll
        for (int nf = 0; nf < 4; nf++)
            #pragma unroll
            for (int e = 0; e < 4; e++) acc[mi][nf][e] = 0.f;

    float fp_acc[8];
    #pragma unroll
    for (int i = 0; i < 8; i++) fp_acc[i] = 0.f;

    int a_row  = lane & 15, a_hi = lane >> 4;
    int b_nloc = (lane & 7) | ((lane >> 1) & 8);
    int b_hi   = (lane >> 3) & 1;

    pj_copy_stage(sb + PJ_STG, S, mbase, by, 0);
    CP_COMMIT();

    for (int kc = 0; kc < 4; kc++) {
        uint32_t stg = sb + PJ_STG + (kc & 1) * PJ_STRIDE;
        char* stgp = smem + PJ_STG + (kc & 1) * PJ_STRIDE;

        CP_WAIT0();
        __syncthreads();

        if (kc < 3) {
            pj_copy_stage(sb + PJ_STG + ((kc + 1) & 1) * PJ_STRIDE, S, mbase, by, kc + 1);
            CP_COMMIT();
        }

        // ---- convert fp32 S chunk -> swizzled fp16, accumulate f partial ----
        #pragma unroll
        for (int i = 0; i < 8; i++) {
            int g = tid + 256 * i;
            int row = g >> 5, cg = g & 31;
            float4 v = *(const float4*)(stgp + PJ_S32 + row * 512 + cg * 16);
            __half2 h01 = __floats2half2_rn(v.x, v.y);
            __half2 h23 = __floats2half2_rn(v.z, v.w);
            uint32_t r01, r23;
            memcpy(&r01, &h01, 4);
            memcpy(&r23, &h23, 4);
            uint32_t a = stg + PJ_SF16 + row * 256 + swz(cg >> 1, row) * 16 + (cg & 1) * 8;
            asm volatile("st.shared.v2.b32 [%0], {%1, %2};"
                         :: "r"(a), "r"(r01), "r"(r23) : "memory");
            if (by == 0) {
                int k0 = kc * 128 + cg * 4;
                fp_acc[i] += v.x * u_s[k0] + v.y * u_s[k0 + 1]
                           + v.z * u_s[k0 + 2] + v.w * u_s[k0 + 3];
            }
        }
        __syncthreads();

        // ---- MMA over this 128-k chunk ----
        #pragma unroll
        for (int ks = 0; ks < 8; ks++) {
            uint32_t Bf[2][4];
            int cB = 2 * ks + b_hi;
            #pragma unroll
            for (int np = 0; np < 2; np++) {
                int nrow = wn * 32 + np * 16 + b_nloc;
                ldsm4(Bf[np], stg + PJ_W + nrow * 256 + swz(cB, nrow) * 16);
            }
            #pragma unroll
            for (int mi = 0; mi < 2; mi++) {
                uint32_t Af[4];
                int qrow = wm * 32 + mi * 16 + a_row;
                int cA = 2 * ks + a_hi;
                ldsm4(Af, stg + PJ_SF16 + qrow * 256 + swz(cA, qrow) * 16);
                #pragma unroll
                for (int nf = 0; nf < 4; nf++)
                    mma_f16(acc[mi][nf], Af, &Bf[nf >> 1][(nf & 1) * 2]);
            }
        }
        __syncthreads();
    }

    if (by == 0) {
        float c = d_u[D_MODEL];
        #pragma unroll
        for (int i = 0; i < 8; i++) {
            float v = fp_acc[i];
            #pragma unroll
            for (int st = 16; st > 0; st >>= 1)
                v += __shfl_xor_sync(0xffffffffu, v, st);
            if (lane == 0) d_f[mbase + w + 8 * i] = v + c;
        }
    }

    __half* OUT = by ? d_K : d_Q;
    #pragma unroll
    for (int mi = 0; mi < 2; mi++)
        #pragma unroll
        for (int nf = 0; nf < 4; nf++)
            #pragma unroll
            for (int hrow = 0; hrow < 2; hrow++) {
                int row = mbase + wm * 32 + mi * 16 + (lane >> 2) + 8 * hrow;
                int col = wn * 32 + nf * 8 + 2 * (lane & 3);
                float v0 = acc[mi][nf][2 * hrow]     + bias_s[col];
                float v1 = acc[mi][nf][2 * hrow + 1] + bias_s[col + 1];
                *(__half2*)(OUT + (size_t)row * DK + col) = __floats2half2_rn(v0, v1);
            }
}

// ============================================================================
// attn: R12 config + fused combine. grid (64 qblocks of 64 rows, 4 chunks),
// 256 thr = 8 warps (2M x 4N), warp tile 32x32, Q fragments cached in 64
// regs, K double-buffered, rk/fk 2-slot ring, 2 CTAs/SM. Last-arriving
// chunk-CTA per qblock combines the 4 partials and writes sigmoid output.
// ============================================================================
#define SM_GATE  0          // 4096
#define SM_RK    4096       // float[2][128] ring
#define SM_FK    5120
#define SM_PL    6144       // float[4][64]
#define SM_PW    7168
#define SM_Q     8192       // 16384
#define SM_K     24576      // 2 x 32768
#define SMEM_TOTAL 90112

__device__ __forceinline__ void cp_tile128(const __half* __restrict__ g,
                                           uint32_t st_base) {
    int tid = threadIdx.x;
    #pragma unroll
    for (int i = 0; i < 8; i++) {
        int idx = tid + 256 * i;
        int row = idx >> 4, c = idx & 15;
        cp16(st_base + row * 256 + swz(c, row) * 16, (const char*)g + row * 256 + c * 16);
    }
}
__device__ __forceinline__ void cp_tile64(const __half* __restrict__ g,
                                          uint32_t st_base) {
    int tid = threadIdx.x;
    #pragma unroll
    for (int i = 0; i < 4; i++) {
        int idx = tid + 256 * i;
        int row = idx >> 4, c = idx & 15;
        cp16(st_base + row * 256 + swz(c, row) * 16, (const char*)g + row * 256 + c * 16);
    }
}

__global__ void __launch_bounds__(256, 2) attn_kernel(const float* __restrict__ ranks,
                                                      const float* __restrict__ wf_b,
                                                      float* __restrict__ out) {
    extern __shared__ __align__(1024) char smem[];
    float* gate_s = (float*)(smem + SM_GATE);
    float* rk_s   = (float*)(smem + SM_RK);   // [2][128] ring
    float* fk_s   = (float*)(smem + SM_FK);
    float* pl_s   = (float*)(smem + SM_PL);   // [4][64]
    float* pw_s   = (float*)(smem + SM_PW);
    uint32_t sb = smem_u32(smem);

    int tid = threadIdx.x;
    int w = tid >> 5, lane = tid & 31;
    int wm = w >> 2, wn = w & 3;          // 2M x 4N warp grid, warp tile 32x32
    int qbase = blockIdx.x * 64;
    int cbase = blockIdx.y * KEYS_PER_CHUNK;

    #pragma unroll
    for (int t = 0; t < 4; t++) gate_s[tid + 256 * t] = d_gate[tid + 256 * t];

    cp_tile64(d_Q + (size_t)qbase * DK, sb + SM_Q);
    cp_tile128(d_K + (size_t)cbase * DK, sb + SM_K);
    if (tid < 128) {
        cp4(sb + SM_RK + tid * 4, ranks + cbase + tid);
        cp4(sb + SM_FK + tid * 4, d_f + cbase + tid);
    }
    CP_COMMIT();

    float rq_t[4];
    #pragma unroll
    for (int s = 0; s < 4; s++)
        rq_t[s] = ranks[qbase + wm * 32 + (s >> 1) * 16 + (lane >> 2) + 8 * (s & 1)] * 0.25f;

    float l_t[4], w_t[4];
    #pragma unroll
    for (int s = 0; s < 4; s++) { l_t[s] = 0.f; w_t[s] = 0.f; }

    float acc[2][4][4];
    #pragma unroll
    for (int mi = 0; mi < 2; mi++)
        #pragma unroll
        for (int nf = 0; nf < 4; nf++)
            #pragma unroll
            for (int e = 0; e < 4; e++) acc[mi][nf][e] = 0.f;

    int a_row  = lane & 15, a_hi = lane >> 4;
    int b_nloc = (lane & 7) | ((lane >> 1) & 8);
    int b_hi   = (lane >> 3) & 1;
    int ccl    = 2 * (lane & 3);

    CP_WAIT0();
    __syncthreads();

    uint32_t Af[2][8][4];
    #pragma unroll
    for (int mi = 0; mi < 2; mi++)
        #pragma unroll
        for (int ks = 0; ks < 8; ks++) {
            int qrow = wm * 32 + mi * 16 + a_row;
            int cA = 2 * ks + a_hi;
            ldsm4(Af[mi][ks], sb + SM_Q + qrow * 256 + swz(cA, qrow) * 16);
        }

    for (int kt = 0; kt < 8; kt++) {
        int buf = kt & 1;
        uint32_t Kb = sb + SM_K + buf * 32768;

        if (kt < 7) {
            int kb = cbase + (kt + 1) * 128;
            int nb = buf ^ 1;
            cp_tile128(d_K + (size_t)kb * DK, sb + SM_K + nb * 32768);
            if (tid < 128) {
                cp4(sb + SM_RK + (nb * 128 + tid) * 4, ranks + kb + tid);
                cp4(sb + SM_FK + (nb * 128 + tid) * 4, d_f + kb + tid);
            }
            CP_COMMIT();
        }

        #pragma unroll
        for (int ks = 0; ks < 8; ks++) {
            uint32_t Bf[2][4];
            int cB = 2 * ks + b_hi;
            #pragma unroll
            for (int np = 0; np < 2; np++) {
                int nrow = wn * 32 + np * 16 + b_nloc;
                ldsm4(Bf[np], Kb + nrow * 256 + swz(cB, nrow) * 16);
            }
            #pragma unroll
            for (int mi = 0; mi < 2; mi++)
                #pragma unroll
                for (int nf = 0; nf < 4; nf++)
                    mma_f16(acc[mi][nf], Af[mi][ks], &Bf[nf >> 1][(nf & 1) * 2]);
        }

        {
            int es = kt & 1;
            float rk_t[8], fk_t[8];
            #pragma unroll
            for (int nf = 0; nf < 4; nf++)
                #pragma unroll
                for (int h = 0; h < 2; h++) {
                    int c = es * 128 + wn * 32 + nf * 8 + ccl + h;
                    rk_t[nf * 2 + h] = rk_s[c] * 0.25f;
                    fk_t[nf * 2 + h] = fk_s[c];
                }
            #pragma unroll
            for (int mi = 0; mi < 2; mi++)
                #pragma unroll
                for (int nf = 0; nf < 4; nf++)
                    #pragma unroll
                    for (int e = 0; e < 4; e++) {
                        int s = mi * 2 + (e >> 1);
                        int ci = nf * 2 + (e & 1);
                        int di = __float2int_rd(fabsf(rq_t[s] - rk_t[ci]));
                        float pr = exp2f(gate_s[di] * acc[mi][nf][e]);
                        l_t[s] += pr;
                        w_t[s] += pr * fk_t[ci];
                        acc[mi][nf][e] = 0.f;
                    }
        }

        CP_WAIT0();
        __syncthreads();
    }

    #pragma unroll
    for (int s = 0; s < 4; s++) {
        #pragma unroll
        for (int st = 1; st < 4; st <<= 1) {
            l_t[s] += __shfl_xor_sync(0xffffffffu, l_t[s], st);
            w_t[s] += __shfl_xor_sync(0xffffffffu, w_t[s], st);
        }
    }
    if ((lane & 3) == 0) {
        #pragma unroll
        for (int s = 0; s < 4; s++) {
            int row = wm * 32 + (s >> 1) * 16 + (lane >> 2) + 8 * (s & 1);
            pl_s[wn * 64 + row] = l_t[s];
            pw_s[wn * 64 + row] = w_t[s];
        }
    }
    __syncthreads();
    if (tid < 64) {
        float L = 0.f, W = 0.f;
        #pragma unroll
        for (int k = 0; k < 4; k++) {
            L += pl_s[k * 64 + tid];
            W += pw_s[k * 64 + tid];
        }
        int idx = blockIdx.y * N_ASSETS + qbase + tid;
        d_pl[idx] = L;
        d_pw[idx] = W;
    }

    // ---- fused combine: last-arriving chunk-CTA of this qblock finishes ----
    __shared__ int is_last;
    __threadfence();                          // partials visible chip-wide
    __syncthreads();                          // all warps' stores included
    if (tid == 0)
        is_last = (atomicAdd(&d_cnt[blockIdx.x], 1) == NCHUNK - 1);
    __syncthreads();
    if (is_last) {
        __threadfence();                      // acquire other chunks' partials
        if (tid < 64) {
            int row = qbase + tid;
            float L = 0.f, W = 0.f;
            #pragma unroll
            for (int c = 0; c < NCHUNK; c++) {
                L += d_pl[c * N_ASSETS + row];
                W += d_pw[c * N_ASSETS + row];
            }
            float z = W / L + wf_b[0];
            out[row] = 1.0f / (1.0f + __expf(-z));
        }
        __syncthreads();
        if (tid == 0) d_cnt[blockIdx.x] = 0;  // reset for next graph replay
    }
}

// ============================================================================
// launch
// ============================================================================
extern "C" void kernel_launch(void* const* d_in, const int* in_sizes, int n_in,
                              void* d_out, int out_size) {
    const float* S        = (const float*)d_in[0];
    const float* ranks    = (const float*)d_in[1];
    const float* Wq_w     = (const float*)d_in[2];
    const float* Wq_b     = (const float*)d_in[3];
    const float* Wk_w     = (const float*)d_in[4];
    const float* Wk_b     = (const float*)d_in[5];
    const float* Wv_w     = (const float*)d_in[6];
    const float* Wv_b     = (const float*)d_in[7];
    const float* rank_emb = (const float*)d_in[8];
    const float* wL_w     = (const float*)d_in[9];
    const float* wL_b     = (const float*)d_in[10];
    const float* wf_w     = (const float*)d_in[11];
    const float* wf_b     = (const float*)d_in[12];
    float* out = (float*)d_out;

    static int attr_set = 0;
    if (!attr_set) {
        cudaFuncSetAttribute(attn_kernel,
                             cudaFuncAttributeMaxDynamicSharedMemorySize, SMEM_TOTAL);
        cudaFuncSetAttribute(proj_mma_kernel,
                             cudaFuncAttributeMaxDynamicSharedMemorySize, PJ_TOTAL);
        attr_set = 1;
    }

    prep_kernel<<<101, 256>>>(rank_emb, wL_w, wL_b, Wv_w, wf_w, Wv_b, Wq_w, Wk_w);
    proj_mma_kernel<<<dim3(64, 2), 256, PJ_TOTAL>>>(S, Wq_b, Wk_b);
    attn_kernel<<<dim3(64, NCHUNK), 256, SMEM_TOTAL>>>(ranks, wf_b, out);
}

// round 17
// speedup vs baseline: 1.0711x; 1.0711x over previous
#include <cuda_runtime.h>
#include <cuda_fp16.h>
#include <cstdint>

// ============================================================================
// CAAN rank-gated attention (sm_100 base: mma.sync fp16 + cp.async):
//   Q,K = fp16( S Wq^T/Wk^T + b )  single-product fp16 HMMA; proj converts
//   fp32 S -> swizzled fp16 smem on the fly and computes f[i]=S[i].u+c inline
//   gate2[d] = log2(e)/sqrt(128) * sigmoid(rank_emb[d].wL+bL)
//   p_ij = exp2( gate2[|ri-rj|/4] * (q_i.k_j) )   (no-max softmax; |arg| small)
//   out_i = sigmoid( (sum_j p f_j)/(sum_j p) + wf_b )
// R16 post-mortem: prep = 8.8us at issue 4.3% => DRAM-latency bound, MLP 2-4
// per thread. R17: full-unroll u-GEMV (32 LDG in flight), float4 gate loads,
// 4x float4 W-convert. attn (27us plateau) + proj + fused combine unchanged.
// Pipeline: prep -> proj -> attn (3 kernels).
// ============================================================================

#define N_ASSETS 4096
#define D_MODEL  512
#define DK       128
#define NUM_EMB  1024
#define NCHUNK   4
#define KEYS_PER_CHUNK (N_ASSETS / NCHUNK)
#define GATE_MUL    0.1275174677682657f      // (1/sqrt(128)) * log2(e)

typedef unsigned long long ull;

// --------------------------- scratch (no allocs) ----------------------------
__device__ __align__(16) __half d_Wf[256 * D_MODEL];   // rows 0-127 Wq, 128-255 Wk
__device__ __align__(16) __half d_Q[N_ASSETS * DK];
__device__ __align__(16) __half d_K[N_ASSETS * DK];
__device__ float d_f[N_ASSETS];
__device__ float d_u[D_MODEL + 1];
__device__ float d_gate[NUM_EMB];            // premultiplied by GATE_MUL
__device__ float d_pl[NCHUNK * N_ASSETS];
__device__ float d_pw[NCHUNK * N_ASSETS];
__device__ int   d_cnt[64];                  // per-qblock arrival counters (self-resetting)

// --------------------------- mma/ldsm/cp.async helpers -----------------------
__device__ __forceinline__ uint32_t smem_u32(const void* p) {
    uint32_t a;
    asm("{ .reg .u64 t; cvta.to.shared.u64 t, %1; cvt.u32.u64 %0, t; }"
        : "=r"(a) : "l"(p));
    return a;
}
__device__ __forceinline__ void ldsm4(uint32_t* r, uint32_t addr) {
    asm volatile("ldmatrix.sync.aligned.m8n8.x4.shared.b16 {%0,%1,%2,%3}, [%4];"
                 : "=r"(r[0]), "=r"(r[1]), "=r"(r[2]), "=r"(r[3]) : "r"(addr));
}
__device__ __forceinline__ void mma_f16(float* c, const uint32_t* a, const uint32_t* b) {
    asm volatile(
        "mma.sync.aligned.m16n8k16.row.col.f32.f16.f16.f32 "
        "{%0,%1,%2,%3}, {%4,%5,%6,%7}, {%8,%9}, {%0,%1,%2,%3};"
        : "+f"(c[0]), "+f"(c[1]), "+f"(c[2]), "+f"(c[3])
        : "r"(a[0]), "r"(a[1]), "r"(a[2]), "r"(a[3]), "r"(b[0]), "r"(b[1]));
}
__device__ __forceinline__ void cp16(uint32_t dst, const void* src) {
    asm volatile("cp.async.cg.shared.global [%0], [%1], 16;" :: "r"(dst), "l"(src));
}
__device__ __forceinline__ void cp4(uint32_t dst, const void* src) {
    asm volatile("cp.async.ca.shared.global [%0], [%1], 4;" :: "r"(dst), "l"(src));
}
#define CP_COMMIT() asm volatile("cp.async.commit_group;" ::: "memory")
#define CP_WAIT0()  asm volatile("cp.async.wait_group 0;" ::: "memory")

// XOR swizzle of 16B-chunk index within a 256B row (16 chunks)
__device__ __forceinline__ int swz(int chunk, int row) {
    return (chunk & 8) | ((chunk ^ row) & 7);
}

// ============================================================================
// prep: gate (b 0-3, float4 loads), u (b 4-35, full-unroll 32 LDG/thread),
//       c (b 36), W fp16 convert (b 37-68, 4x float4/thread)
// ============================================================================
__global__ void prep_kernel(const float* __restrict__ rank_emb,
                            const float* __restrict__ wL_w,
                            const float* __restrict__ wL_b,
                            const float* __restrict__ Wv_w,
                            const float* __restrict__ wf_w,
                            const float* __restrict__ Wv_b,
                            const float* __restrict__ Wq_w,
                            const float* __restrict__ Wk_w) {
    int b = blockIdx.x, t = threadIdx.x;
    if (b < 4) {
        int d = b * 256 + t;
        float s = wL_b[0];
        #pragma unroll
        for (int e4 = 0; e4 < 8; e4++) {
            float4 v  = ((const float4*)rank_emb)[d * 8 + e4];
            float4 wv = ((const float4*)wL_w)[e4];
            s += v.x * wv.x + v.y * wv.y + v.z * wv.z + v.w * wv.w;
        }
        d_gate[d] = GATE_MUL / (1.0f + __expf(-s));
    } else if (b < 36) {
        // u[m] = sum_o Wv[o][m] wf[o]; 16 m per block, 16-way o split, MLP 32
        int b2 = b - 4;
        int mloc = t & 15, oo = t >> 4;
        int m = b2 * 16 + mloc;
        float s = 0.f;
        #pragma unroll
        for (int i = 0; i < 32; i++) {
            int o = oo + 16 * i;
            s += Wv_w[o * D_MODEL + m] * wf_w[o];
        }
        __shared__ float red[256];
        red[t] = s; __syncthreads();
        if (t < 16) {
            float x = red[t];
            #pragma unroll
            for (int i = 1; i < 16; i++) x += red[t + 16 * i];
            d_u[m] = x;
        }
    } else if (b == 36) {
        __shared__ float red[256];
        float s = 0.f;
        for (int o = t; o < D_MODEL; o += 256) s += wf_w[o] * Wv_b[o];
        red[t] = s; __syncthreads();
        for (int st = 128; st > 0; st >>= 1) {
            if (t < st) red[t] += red[t + st];
            __syncthreads();
        }
        if (t == 0) d_u[D_MODEL] = red[0];
    } else {
        // W convert: 32 blocks x 256 thr x 16 elems (4 float4 loads in flight)
        int g0 = (b - 37) * 4096 + t * 16;
        float4 v[4];
        #pragma unroll
        for (int j = 0; j < 4; j++)
            v[j] = (g0 < 65536)
                ? *(const float4*)(Wq_w + g0 + 4 * j)
                : *(const float4*)(Wk_w + g0 + 4 * j - 65536);
        #pragma unroll
        for (int j = 0; j < 4; j++) {
            __half2* dst = (__half2*)(d_Wf + g0 + 4 * j);
            dst[0] = __floats2half2_rn(v[j].x, v[j].y);
            dst[1] = __floats2half2_rn(v[j].z, v[j].w);
        }
    }
}

// ============================================================================
// proj_mma: Q/K = fp16( S @ W^T + b ). Stages fp32 S via cp.async, converts
// to swizzled fp16 smem in-kernel, computes f[i]=S[i].u+c inline (by==0).
// grid (64 M-tiles of 64 rows, 2 = {Q,K}), 256 thr = 8 warps (2M x 4N).
// ============================================================================
#define PJ_BIAS   0          // 512B
#define PJ_U      512        // 513 floats (u + c)
#define PJ_STG    4096
#define PJ_STRIDE 81920      // SF16 16K | W 32K | S32 32K
#define PJ_SF16   0
#define PJ_W      16384
#define PJ_S32    49152
#define PJ_TOTAL  (4096 + 2 * 81920)   // 167936

__device__ __forceinline__ void pj_copy_stage(uint32_t stg, const float* __restrict__ S,
                                              int mbase, int by, int kc) {
    int tid = threadIdx.x;
    #pragma unroll
    for (int i = 0; i < 8; i++) {
        int idx = tid + 256 * i;
        int row = idx >> 4, c = idx & 15;
        const __half* g = d_Wf + (size_t)(by * 128 + row) * D_MODEL + kc * 128 + c * 8;
        cp16(stg + PJ_W + row * 256 + swz(c, row) * 16, g);
    }
    #pragma unroll
    for (int i = 0; i < 8; i++) {
        int idx = tid + 256 * i;
        int row = idx >> 5, c = idx & 31;
        const float* g = S + (size_t)(mbase + row) * D_MODEL + kc * 128 + c * 4;
        cp16(stg + PJ_S32 + row * 512 + c * 16, g);
    }
}

__global__ void __launch_bounds__(256, 1) proj_mma_kernel(
    const float* __restrict__ S,
    const float* __restrict__ Wq_b, const float* __restrict__ Wk_b) {
    extern __shared__ __align__(1024) char smem[];
    uint32_t sb = smem_u32(smem);
    float* bias_s = (float*)(smem + PJ_BIAS);
    float* u_s    = (float*)(smem + PJ_U);

    int tid = threadIdx.x;
    int w = tid >> 5, lane = tid & 31;
    int wm = w >> 2, wn = w & 3;
    int mbase = blockIdx.x * 64;
    int by = blockIdx.y;                 // 0 = Q, 1 = K

    if (tid < 128) bias_s[tid] = (by ? Wk_b : Wq_b)[tid];
    u_s[tid] = d_u[tid];
    u_s[tid + 256] = d_u[tid + 256];

    float acc[2][4][4];
    #pragma unroll
    for (int mi = 0; mi < 2; mi++)
        #pragma unroll
        for (int nf = 0; nf < 4; nf++)
            #pragma unroll
            for (int e = 0; e < 4; e++) acc[mi][nf][e] = 0.f;

    float fp_acc[8];
    #pragma unroll
    for (int i = 0; i < 8; i++) fp_acc[i] = 0.f;

    int a_row  = lane & 15, a_hi = lane >> 4;
    int b_nloc = (lane & 7) | ((lane >> 1) & 8);
    int b_hi   = (lane >> 3) & 1;

    pj_copy_stage(sb + PJ_STG, S, mbase, by, 0);
    CP_COMMIT();

    for (int kc = 0; kc < 4; kc++) {
        uint32_t stg = sb + PJ_STG + (kc & 1) * PJ_STRIDE;
        char* stgp = smem + PJ_STG + (kc & 1) * PJ_STRIDE;

        CP_WAIT0();
        __syncthreads();

        if (kc < 3) {
            pj_copy_stage(sb + PJ_STG + ((kc + 1) & 1) * PJ_STRIDE, S, mbase, by, kc + 1);
            CP_COMMIT();
        }

        // ---- convert fp32 S chunk -> swizzled fp16, accumulate f partial ----
        #pragma unroll
        for (int i = 0; i < 8; i++) {
            int g = tid + 256 * i;
            int row = g >> 5, cg = g & 31;
            float4 v = *(const float4*)(stgp + PJ_S32 + row * 512 + cg * 16);
            __half2 h01 = __floats2half2_rn(v.x, v.y);
            __half2 h23 = __floats2half2_rn(v.z, v.w);
            uint32_t r01, r23;
            memcpy(&r01, &h01, 4);
            memcpy(&r23, &h23, 4);
            uint32_t a = stg + PJ_SF16 + row * 256 + swz(cg >> 1, row) * 16 + (cg & 1) * 8;
            asm volatile("st.shared.v2.b32 [%0], {%1, %2};"
                         :: "r"(a), "r"(r01), "r"(r23) : "memory");
            if (by == 0) {
                int k0 = kc * 128 + cg * 4;
                fp_acc[i] += v.x * u_s[k0] + v.y * u_s[k0 + 1]
                           + v.z * u_s[k0 + 2] + v.w * u_s[k0 + 3];
            }
        }
        __syncthreads();

        // ---- MMA over this 128-k chunk ----
        #pragma unroll
        for (int ks = 0; ks < 8; ks++) {
            uint32_t Bf[2][4];
            int cB = 2 * ks + b_hi;
            #pragma unroll
            for (int np = 0; np < 2; np++) {
                int nrow = wn * 32 + np * 16 + b_nloc;
                ldsm4(Bf[np], stg + PJ_W + nrow * 256 + swz(cB, nrow) * 16);
            }
            #pragma unroll
            for (int mi = 0; mi < 2; mi++) {
                uint32_t Af[4];
                int qrow = wm * 32 + mi * 16 + a_row;
                int cA = 2 * ks + a_hi;
                ldsm4(Af, stg + PJ_SF16 + qrow * 256 + swz(cA, qrow) * 16);
                #pragma unroll
                for (int nf = 0; nf < 4; nf++)
                    mma_f16(acc[mi][nf], Af, &Bf[nf >> 1][(nf & 1) * 2]);
            }
        }
        __syncthreads();
    }

    if (by == 0) {
        float c = d_u[D_MODEL];
        #pragma unroll
        for (int i = 0; i < 8; i++) {
            float v = fp_acc[i];
            #pragma unroll
            for (int st = 16; st > 0; st >>= 1)
                v += __shfl_xor_sync(0xffffffffu, v, st);
            if (lane == 0) d_f[mbase + w + 8 * i] = v + c;
        }
    }

    __half* OUT = by ? d_K : d_Q;
    #pragma unroll
    for (int mi = 0; mi < 2; mi++)
        #pragma unroll
        for (int nf = 0; nf < 4; nf++)
            #pragma unroll
            for (int hrow = 0; hrow < 2; hrow++) {
                int row = mbase + wm * 32 + mi * 16 + (lane >> 2) + 8 * hrow;
                int col = wn * 32 + nf * 8 + 2 * (lane & 3);
                float v0 = acc[mi][nf][2 * hrow]     + bias_s[col];
                float v1 = acc[mi][nf][2 * hrow + 1] + bias_s[col + 1];
                *(__half2*)(OUT + (size_t)row * DK + col) = __floats2half2_rn(v0, v1);
            }
}

// ============================================================================
// attn: R12 config + fused combine. grid (64 qblocks of 64 rows, 4 chunks),
// 256 thr = 8 warps (2M x 4N), warp tile 32x32, Q fragments cached in 64
// regs, K double-buffered, rk/fk 2-slot ring, 2 CTAs/SM. Last-arriving
// chunk-CTA per qblock combines the 4 partials and writes sigmoid output.
// ============================================================================
#define SM_GATE  0          // 4096
#define SM_RK    4096       // float[2][128] ring
#define SM_FK    5120
#define SM_PL    6144       // float[4][64]
#define SM_PW    7168
#define SM_Q     8192       // 16384
#define SM_K     24576      // 2 x 32768
#define SMEM_TOTAL 90112

__device__ __forceinline__ void cp_tile128(const __half* __restrict__ g,
                                           uint32_t st_base) {
    int tid = threadIdx.x;
    #pragma unroll
    for (int i = 0; i < 8; i++) {
        int idx = tid + 256 * i;
        int row = idx >> 4, c = idx & 15;
        cp16(st_base + row * 256 + swz(c, row) * 16, (const char*)g + row * 256 + c * 16);
    }
}
__device__ __forceinline__ void cp_tile64(const __half* __restrict__ g,
                                          uint32_t st_base) {
    int tid = threadIdx.x;
    #pragma unroll
    for (int i = 0; i < 4; i++) {
        int idx = tid + 256 * i;
        int row = idx >> 4, c = idx & 15;
        cp16(st_base + row * 256 + swz(c, row) * 16, (const char*)g + row * 256 + c * 16);
    }
}

__global__ void __launch_bounds__(256, 2) attn_kernel(const float* __restrict__ ranks,
                                                      const float* __restrict__ wf_b,
                                                      float* __restrict__ out) {
    extern __shared__ __align__(1024) char smem[];
    float* gate_s = (float*)(smem + SM_GATE);
    float* rk_s   = (float*)(smem + SM_RK);   // [2][128] ring
    float* fk_s   = (float*)(smem + SM_FK);
    float* pl_s   = (float*)(smem + SM_PL);   // [4][64]
    float* pw_s   = (float*)(smem + SM_PW);
    uint32_t sb = smem_u32(smem);

    int tid = threadIdx.x;
    int w = tid >> 5, lane = tid & 31;
    int wm = w >> 2, wn = w & 3;          // 2M x 4N warp grid, warp tile 32x32
    int qbase = blockIdx.x * 64;
    int cbase = blockIdx.y * KEYS_PER_CHUNK;

    #pragma unroll
    for (int t = 0; t < 4; t++) gate_s[tid + 256 * t] = d_gate[tid + 256 * t];

    cp_tile64(d_Q + (size_t)qbase * DK, sb + SM_Q);
    cp_tile128(d_K + (size_t)cbase * DK, sb + SM_K);
    if (tid < 128) {
        cp4(sb + SM_RK + tid * 4, ranks + cbase + tid);
        cp4(sb + SM_FK + tid * 4, d_f + cbase + tid);
    }
    CP_COMMIT();

    float rq_t[4];
    #pragma unroll
    for (int s = 0; s < 4; s++)
        rq_t[s] = ranks[qbase + wm * 32 + (s >> 1) * 16 + (lane >> 2) + 8 * (s & 1)] * 0.25f;

    float l_t[4], w_t[4];
    #pragma unroll
    for (int s = 0; s < 4; s++) { l_t[s] = 0.f; w_t[s] = 0.f; }

    float acc[2][4][4];
    #pragma unroll
    for (int mi = 0; mi < 2; mi++)
        #pragma unroll
        for (int nf = 0; nf < 4; nf++)
            #pragma unroll
            for (int e = 0; e < 4; e++) acc[mi][nf][e] = 0.f;

    int a_row  = lane & 15, a_hi = lane >> 4;
    int b_nloc = (lane & 7) | ((lane >> 1) & 8);
    int b_hi   = (lane >> 3) & 1;
    int ccl    = 2 * (lane & 3);

    CP_WAIT0();
    __syncthreads();

    uint32_t Af[2][8][4];
    #pragma unroll
    for (int mi = 0; mi < 2; mi++)
        #pragma unroll
        for (int ks = 0; ks < 8; ks++) {
            int qrow = wm * 32 + mi * 16 + a_row;
            int cA = 2 * ks + a_hi;
            ldsm4(Af[mi][ks], sb + SM_Q + qrow * 256 + swz(cA, qrow) * 16);
        }

    for (int kt = 0; kt < 8; kt++) {
        int buf = kt & 1;
        uint32_t Kb = sb + SM_K + buf * 32768;

        if (kt < 7) {
            int kb = cbase + (kt + 1) * 128;
            int nb = buf ^ 1;
            cp_tile128(d_K + (size_t)kb * DK, sb + SM_K + nb * 32768);
            if (tid < 128) {
                cp4(sb + SM_RK + (nb * 128 + tid) * 4, ranks + kb + tid);
                cp4(sb + SM_FK + (nb * 128 + tid) * 4, d_f + kb + tid);
            }
            CP_COMMIT();
        }

        #pragma unroll
        for (int ks = 0; ks < 8; ks++) {
            uint32_t Bf[2][4];
            int cB = 2 * ks + b_hi;
            #pragma unroll
            for (int np = 0; np < 2; np++) {
                int nrow = wn * 32 + np * 16 + b_nloc;
                ldsm4(Bf[np], Kb + nrow * 256 + swz(cB, nrow) * 16);
            }
            #pragma unroll
            for (int mi = 0; mi < 2; mi++)
                #pragma unroll
                for (int nf = 0; nf < 4; nf++)
                    mma_f16(acc[mi][nf], Af[mi][ks], &Bf[nf >> 1][(nf & 1) * 2]);
        }

        {
            int es = kt & 1;
            float rk_t[8], fk_t[8];
            #pragma unroll
            for (int nf = 0; nf < 4; nf++)
                #pragma unroll
                for (int h = 0; h < 2; h++) {
                    int c = es * 128 + wn * 32 + nf * 8 + ccl + h;
                    rk_t[nf * 2 + h] = rk_s[c] * 0.25f;
                    fk_t[nf * 2 + h] = fk_s[c];
                }
            #pragma unroll
            for (int mi = 0; mi < 2; mi++)
                #pragma unroll
                for (int nf = 0; nf < 4; nf++)
                    #pragma unroll
                    for (int e = 0; e < 4; e++) {
                        int s = mi * 2 + (e >> 1);
                        int ci = nf * 2 + (e & 1);
                        int di = __float2int_rd(fabsf(rq_t[s] - rk_t[ci]));
                        float pr = exp2f(gate_s[di] * acc[mi][nf][e]);
                        l_t[s] += pr;
                        w_t[s] += pr * fk_t[ci];
                        acc[mi][nf][e] = 0.f;
                    }
        }

        CP_WAIT0();
        __syncthreads();
    }

    #pragma unroll
    for (int s = 0; s < 4; s++) {
        #pragma unroll
        for (int st = 1; st < 4; st <<= 1) {
            l_t[s] += __shfl_xor_sync(0xffffffffu, l_t[s], st);
            w_t[s] += __shfl_xor_sync(0xffffffffu, w_t[s], st);
        }
    }
    if ((lane & 3) == 0) {
        #pragma unroll
        for (int s = 0; s < 4; s++) {
            int row = wm * 32 + (s >> 1) * 16 + (lane >> 2) + 8 * (s & 1);
            pl_s[wn * 64 + row] = l_t[s];
            pw_s[wn * 64 + row] = w_t[s];
        }
    }
    __syncthreads();
    if (tid < 64) {
        float L = 0.f, W = 0.f;
        #pragma unroll
        for (int k = 0; k < 4; k++) {
            L += pl_s[k * 64 + tid];
            W += pw_s[k * 64 + tid];
        }
        int idx = blockIdx.y * N_ASSETS + qbase + tid;
        d_pl[idx] = L;
        d_pw[idx] = W;
    }

    // ---- fused combine: last-arriving chunk-CTA of this qblock finishes ----
    __shared__ int is_last;
    __threadfence();
    __syncthreads();
    if (tid == 0)
        is_last = (atomicAdd(&d_cnt[blockIdx.x], 1) == NCHUNK - 1);
    __syncthreads();
    if (is_last) {
        __threadfence();
        if (tid < 64) {
            int row = qbase + tid;
            float L = 0.f, W = 0.f;
            #pragma unroll
            for (int c = 0; c < NCHUNK; c++) {
                L += d_pl[c * N_ASSETS + row];
                W += d_pw[c * N_ASSETS + row];
            }
            float z = W / L + wf_b[0];
            out[row] = 1.0f / (1.0f + __expf(-z));
        }
        __syncthreads();
        if (tid == 0) d_cnt[blockIdx.x] = 0;
    }
}

// ============================================================================
// launch
// ============================================================================
extern "C" void kernel_launch(void* const* d_in, const int* in_sizes, int n_in,
                              void* d_out, int out_size) {
    const float* S        = (const float*)d_in[0];
    const float* ranks    = (const float*)d_in[1];
    const float* Wq_w     = (const float*)d_in[2];
    const float* Wq_b     = (const float*)d_in[3];
    const float* Wk_w     = (const float*)d_in[4];
    const float* Wk_b     = (const float*)d_in[5];
    const float* Wv_w     = (const float*)d_in[6];
    const float* Wv_b     = (const float*)d_in[7];
    const float* rank_emb = (const float*)d_in[8];
    const float* wL_w     = (const float*)d_in[9];
    const float* wL_b     = (const float*)d_in[10];
    const float* wf_w     = (const float*)d_in[11];
    const float* wf_b     = (const float*)d_in[12];
    float* out = (float*)d_out;

    static int attr_set = 0;
    if (!attr_set) {
        cudaFuncSetAttribute(attn_kernel,
                             cudaFuncAttributeMaxDynamicSharedMemorySize, SMEM_TOTAL);
        cudaFuncSetAttribute(proj_mma_kernel,
                             cudaFuncAttributeMaxDynamicSharedMemorySize, PJ_TOTAL);
        attr_set = 1;
    }

    prep_kernel<<<69, 256>>>(rank_emb, wL_w, wL_b, Wv_w, wf_w, Wv_b, Wq_w, Wk_w);
    proj_mma_kernel<<<dim3(64, 2), 256, PJ_TOTAL>>>(S, Wq_b, Wk_b);
    attn_kernel<<<dim3(64, NCHUNK), 256, SMEM_TOTAL>>>(ranks, wf_b, out);
}